// round 2
// baseline (speedup 1.0000x reference)
#include <cuda_runtime.h>

// g_M: two real 3x3 bilinear forms (observable Z0 and Z1), padded to 20 floats.
// z_k = (1, X0, Y0) * M_k * (1, X1, Y1)^T,  X = cos(pi*n), Y = sin(pi*n).
__device__ float g_M[20];

__device__ __forceinline__ float2 cmul(float2 a, float2 b) {
    return make_float2(a.x * b.x - a.y * b.y, a.x * b.y + a.y * b.x);
}
__device__ __forceinline__ float2 cadd(float2 a, float2 b) {
    return make_float2(a.x + b.x, a.y + b.y);
}

// One-thread prep: compose W = L2*L1*D (4x4 complex), then reduce each
// observable to a real 3x3 bilinear form M.
__global__ void prep_kernel(const float* __restrict__ qw) {
    if (threadIdx.x != 0 || blockIdx.x != 0) return;

    float2 W[4][4];
    #pragma unroll
    for (int i = 0; i < 4; i++)
        #pragma unroll
        for (int j = 0; j < 4; j++)
            W[i][j] = make_float2(0.f, 0.f);
    // D = diag(1, -i, -i, -1): folds the -i factors of RX|0> amplitudes.
    W[0][0] = make_float2(1.f, 0.f);
    W[1][1] = make_float2(0.f, -1.f);
    W[2][2] = make_float2(0.f, -1.f);
    W[3][3] = make_float2(-1.f, 0.f);

    for (int l = 0; l < 2; l++) {
        float2 g[2][2][2];
        for (int w = 0; w < 2; w++) {
            float phi = qw[l * 6 + w * 3 + 0];
            float th  = qw[l * 6 + w * 3 + 1];
            float om  = qw[l * 6 + w * 3 + 2];
            float ct = cosf(0.5f * th), st = sinf(0.5f * th);
            float a = 0.5f * (phi + om), b = 0.5f * (phi - om);
            float ca = cosf(a), sa = sinf(a), cb = cosf(b), sb = sinf(b);
            g[w][0][0] = make_float2(ct * ca, -ct * sa);
            g[w][0][1] = make_float2(-st * cb, -st * sb);
            g[w][1][0] = make_float2(st * cb, -st * sb);
            g[w][1][1] = make_float2(ct * ca,  ct * sa);
        }

        float2 T[4][4], W2[4][4];
        for (int i = 0; i < 2; i++)
            for (int j = 0; j < 2; j++)
                for (int m = 0; m < 4; m++)
                    T[i * 2 + j][m] = cadd(cmul(g[0][i][0], W[0 * 2 + j][m]),
                                           cmul(g[0][i][1], W[1 * 2 + j][m]));
        for (int i = 0; i < 2; i++)
            for (int j = 0; j < 2; j++)
                for (int m = 0; m < 4; m++)
                    W2[i * 2 + j][m] = cadd(cmul(g[1][j][0], T[i * 2 + 0][m]),
                                            cmul(g[1][j][1], T[i * 2 + 1][m]));
        // CNOT(c=0,t=1): new[(i,j)] = old[(i, j^i)]
        for (int i = 0; i < 2; i++)
            for (int j = 0; j < 2; j++)
                for (int m = 0; m < 4; m++)
                    T[i * 2 + j][m] = W2[i * 2 + (j ^ i)][m];
        // CNOT(c=1,t=0): new[(i,j)] = old[(i^j, j)]
        for (int i = 0; i < 2; i++)
            for (int j = 0; j < 2; j++)
                for (int m = 0; m < 4; m++)
                    W[i * 2 + j][m] = T[(i ^ j) * 2 + j][m];
    }

    // u_a*u_b expressed in basis (1, X, Y):  c^2=(1+X)/2, cs=Y/2, s^2=(1-X)/2
    const float Qu[2][2][3] = {
        { {0.5f, 0.5f, 0.f}, {0.f, 0.f, 0.5f} },
        { {0.f, 0.f, 0.5f},  {0.5f, -0.5f, 0.f} }
    };

    for (int obs = 0; obs < 2; obs++) {
        float s[4];
        if (obs == 0) { s[0] = 1; s[1] = 1;  s[2] = -1; s[3] = -1; }
        else          { s[0] = 1; s[1] = -1; s[2] = 1;  s[3] = -1; }

        // ReA[j][m] = Re( (W^H S W)[j][m] )
        float ReA[4][4];
        for (int j = 0; j < 4; j++)
            for (int m = 0; m < 4; m++) {
                float acc = 0.f;
                for (int k = 0; k < 4; k++)
                    acc += s[k] * (W[k][j].x * W[k][m].x + W[k][j].y * W[k][m].y);
                ReA[j][m] = acc;
            }

        // Project quadratic form in r = u (x) v onto bilinear form in
        // (1,X0,Y0) x (1,X1,Y1).
        float M[3][3] = {};
        for (int a = 0; a < 2; a++)
            for (int b = 0; b < 2; b++)
                for (int c = 0; c < 2; c++)
                    for (int d = 0; d < 2; d++)
                        for (int al = 0; al < 3; al++)
                            for (int be = 0; be < 3; be++)
                                M[al][be] += ReA[2 * a + c][2 * b + d]
                                           * Qu[a][b][al] * Qu[c][d][be];

        for (int al = 0; al < 3; al++)
            for (int be = 0; be < 3; be++)
                g_M[obs * 9 + al * 3 + be] = M[al][be];
    }
    g_M[18] = 0.f;
    g_M[19] = 0.f;
}

__device__ __forceinline__ float bil(const float* __restrict__ m,
                                     float X0, float Y0, float X1, float Y1) {
    float d0 = fmaf(m[2], Y1, fmaf(m[1], X1, m[0]));
    float d1 = fmaf(m[5], Y1, fmaf(m[4], X1, m[3]));
    float d2 = fmaf(m[8], Y1, fmaf(m[7], X1, m[6]));
    return fmaf(Y0, d2, fmaf(X0, d1, d0));
}

__device__ __forceinline__ void eval_f4(float4 nz, const float* __restrict__ M,
                                        float4& res) {
    const float PI = 3.14159265358979323846f;
    float X0, Y0, X1, Y1, X2, Y2, X3, Y3;
    __sincosf(nz.x * PI, &Y0, &X0);
    __sincosf(nz.y * PI, &Y1, &X1);
    __sincosf(nz.z * PI, &Y2, &X2);
    __sincosf(nz.w * PI, &Y3, &X3);
    res.x = bil(M + 0, X0, Y0, X1, Y1);
    res.y = bil(M + 9, X0, Y0, X1, Y1);
    res.z = bil(M + 0, X2, Y2, X3, Y3);
    res.w = bil(M + 9, X2, Y2, X3, Y3);
}

// 4 samples per thread: two float4 streams (split-array for coalescing).
__global__ void __launch_bounds__(256) qcirc_kernel(
    const float4* __restrict__ noise, float4* __restrict__ out, int t)
{
    int idx = blockIdx.x * blockDim.x + threadIdx.x;
    if (idx >= t) return;

    // Uniform bilinear-form coefficients: 5 x float4 (L1/L2-resident).
    float M[20];
    const float4* mp = reinterpret_cast<const float4*>(g_M);
    #pragma unroll
    for (int i = 0; i < 5; i++) {
        float4 v = __ldg(&mp[i]);
        M[4 * i + 0] = v.x; M[4 * i + 1] = v.y;
        M[4 * i + 2] = v.z; M[4 * i + 3] = v.w;
    }

    float4 a = noise[idx];
    float4 b = noise[idx + t];
    float4 ra, rb;
    eval_f4(a, M, ra);
    eval_f4(b, M, rb);
    out[idx] = ra;
    out[idx + t] = rb;
}

extern "C" void kernel_launch(void* const* d_in, const int* in_sizes, int n_in,
                              void* d_out, int out_size) {
    const float* noise = (const float*)d_in[0];     // [B, 2] f32
    const float* qw    = (const float*)d_in[1];     // [2, 2, 3] f32

    prep_kernel<<<1, 32>>>(qw);

    int n4 = in_sizes[0] / 4;   // number of float4s (2 samples each)
    int t = n4 / 2;             // threads: 4 samples per thread
    int threads = 256;
    int blocks = (t + threads - 1) / threads;
    qcirc_kernel<<<blocks, threads>>>(
        (const float4*)noise, (float4*)d_out, t);
}